// round 6
// baseline (speedup 1.0000x reference)
#include <cuda_runtime.h>

#define HEADS 8
#define CH 32
#define CH4 8              // float4 chunks per row
#define NMAX 50000
#define EMAX 400000

__device__ float4 g_kn4[NMAX * HEADS * CH4];  // RMSNorm'd K, float4 layout
__device__ int    g_rowptr[NMAX + 1];

// ---------------------------------------------------------------------------
// Kernel 1: kn = RMSNorm(k)*w_k — warp handles 8 rows: lane group g (0..3)
// owns rows warp*8+g and warp*8+4+g (two independent chains per lane).
// ---------------------------------------------------------------------------
__global__ void kn_kernel(const float4* __restrict__ k4,
                          const float4* __restrict__ w4,
                          int nrows) {
    int warp = blockIdx.x * (blockDim.x >> 5) + (threadIdx.x >> 5);
    int lane = threadIdx.x & 31;
    int g = lane >> 3;
    int i = lane & 7;
    int r0 = warp * 8 + g;
    int r1 = r0 + 4;
    if (r0 >= nrows) return;
    bool has1 = r1 < nrows;

    float4 x0 = k4[r0 * CH4 + i];
    float4 x1 = has1 ? k4[r1 * CH4 + i] : make_float4(0.f, 0.f, 0.f, 0.f);

    float s0 = x0.x * x0.x + x0.y * x0.y + x0.z * x0.z + x0.w * x0.w;
    float s1 = x1.x * x1.x + x1.y * x1.y + x1.z * x1.z + x1.w * x1.w;
#pragma unroll
    for (int o = 1; o <= 4; o <<= 1) {
        s0 += __shfl_xor_sync(0xffffffffu, s0, o);
        s1 += __shfl_xor_sync(0xffffffffu, s1, o);
    }
    float r0v = rsqrtf(s0 * (1.0f / CH) + 1e-6f);
    float r1v = rsqrtf(s1 * (1.0f / CH) + 1e-6f);
    float4 w = w4[i];
    float4 y0, y1;
    y0.x = x0.x * r0v * w.x; y0.y = x0.y * r0v * w.y;
    y0.z = x0.z * r0v * w.z; y0.w = x0.w * r0v * w.w;
    g_kn4[r0 * CH4 + i] = y0;
    if (has1) {
        y1.x = x1.x * r1v * w.x; y1.y = x1.y * r1v * w.y;
        y1.z = x1.z * r1v * w.z; y1.w = x1.w * r1v * w.w;
        g_kn4[r1 * CH4 + i] = y1;
    }
}

// ---------------------------------------------------------------------------
// Kernel 2: row_ptr[d] = lower_bound(edge_dst, d)
// ---------------------------------------------------------------------------
__global__ void rowptr_kernel(const int* __restrict__ dst, int E, int N) {
    int d = blockIdx.x * blockDim.x + threadIdx.x;
    if (d > N) return;
    int lo = 0, hi = E;
    while (lo < hi) {
        int mid = (lo + hi) >> 1;
        if (dst[mid] < d) lo = mid + 1; else hi = mid;
    }
    g_rowptr[d] = lo;
}

// ---------------------------------------------------------------------------
// Kernel 3: block = dst, warp = head; lane = g*8+i (g = edge slot, i = chunk).
// Register double-buffered: batch n+1's loads are issued before batch n's
// SHFL/exp/FMA consume phase, keeping loads in flight continuously.
// No running max (scores are O(8); fp32 exp cannot overflow).
// ---------------------------------------------------------------------------
__global__ void attn_kernel(const float4* __restrict__ q4,
                            const float4* __restrict__ v4,
                            const float4* __restrict__ e4,
                            const float4* __restrict__ wq4,
                            const int*    __restrict__ src,
                            float4* __restrict__ out4) {
    const int d    = blockIdx.x;
    const int h    = threadIdx.x >> 5;
    const int lane = threadIdx.x & 31;
    const int g    = lane >> 3;
    const int i    = lane & 7;

    const int start = g_rowptr[d];
    const int end   = g_rowptr[d + 1];

    // issue q load immediately
    float4 qv = q4[(d * HEADS + h) * CH4 + i];

    // ---- prologue: issue batch 0 loads before the q-norm shuffles ----
    int    cs = 0;
    float4 cev = make_float4(0.f, 0.f, 0.f, 0.f);
    float4 ckn = cev, cvv = cev;
    float  cval = 0.0f;
    if (start < end) {
        int me = start + g;
        int ce = me < end ? me : end - 1;
        cval = (me < end) ? 1.0f : 0.0f;
        cs  = src[ce];
        cev = __ldcs(&e4[(ce * HEADS + h) * CH4 + i]);
        ckn = g_kn4[(cs * HEADS + h) * CH4 + i];
        cvv = v4[(cs * HEADS + h) * CH4 + i];
    }

    // RMSNorm(q) — overlaps with batch-0 loads
    float ss = qv.x * qv.x + qv.y * qv.y + qv.z * qv.z + qv.w * qv.w;
#pragma unroll
    for (int o = 1; o <= 4; o <<= 1) ss += __shfl_xor_sync(0xffffffffu, ss, o);
    float rq = rsqrtf(ss * (1.0f / CH) + 1e-6f);
    float4 w = wq4[i];
    float4 qn;
    qn.x = qv.x * rq * w.x; qn.y = qv.y * rq * w.y;
    qn.z = qv.z * rq * w.z; qn.w = qv.w * rq * w.w;

    const float scale = 0.1767766952966369f;  // 1/sqrt(32)

    float  l = 0.0f;
    float4 acc = make_float4(0.f, 0.f, 0.f, 0.f);

    for (int eid = start; eid < end; eid += 4) {
        // ---- issue next batch's loads first ----
        int    ns = 0;
        float4 nev = make_float4(0.f, 0.f, 0.f, 0.f);
        float4 nkn = nev, nvv = nev;
        float  nval = 0.0f;
        int neid = eid + 4;
        if (neid < end) {
            int me = neid + g;
            int ne = me < end ? me : end - 1;
            nval = (me < end) ? 1.0f : 0.0f;
            ns  = src[ne];
            nev = __ldcs(&e4[(ne * HEADS + h) * CH4 + i]);
            nkn = g_kn4[(ns * HEADS + h) * CH4 + i];
            nvv = v4[(ns * HEADS + h) * CH4 + i];
        }

        // ---- consume current batch ----
        float p = qn.x * (ckn.x + cev.x);
        p = fmaf(qn.y, ckn.y + cev.y, p);
        p = fmaf(qn.z, ckn.z + cev.z, p);
        p = fmaf(qn.w, ckn.w + cev.w, p);
#pragma unroll
        for (int o = 1; o <= 4; o <<= 1) p += __shfl_xor_sync(0xffffffffu, p, o);

        float pe = __expf(p * scale) * cval;   // clamped loads are real -> finite

        l += pe;
        acc.x = fmaf(pe, cvv.x + cev.x, acc.x);
        acc.y = fmaf(pe, cvv.y + cev.y, acc.y);
        acc.z = fmaf(pe, cvv.z + cev.z, acc.z);
        acc.w = fmaf(pe, cvv.w + cev.w, acc.w);

        // rotate buffers
        cs = ns; cev = nev; ckn = nkn; cvv = nvv; cval = nval;
    }

    // combine the 4 edge-groups
#pragma unroll
    for (int o = 8; o <= 16; o <<= 1) {
        l     += __shfl_xor_sync(0xffffffffu, l, o);
        acc.x += __shfl_xor_sync(0xffffffffu, acc.x, o);
        acc.y += __shfl_xor_sync(0xffffffffu, acc.y, o);
        acc.z += __shfl_xor_sync(0xffffffffu, acc.z, o);
        acc.w += __shfl_xor_sync(0xffffffffu, acc.w, o);
    }

    if (g == 0) {
        float inv = (l > 0.0f) ? 1.0f / l : 0.0f;
        float4 o;
        o.x = acc.x * inv; o.y = acc.y * inv;
        o.z = acc.z * inv; o.w = acc.w * inv;
        out4[(d * HEADS + h) * CH4 + i] = o;
    }
}

// ---------------------------------------------------------------------------
extern "C" void kernel_launch(void* const* d_in, const int* in_sizes, int n_in,
                              void* d_out, int out_size) {
    const float* q    = (const float*)d_in[0];
    const float* k    = (const float*)d_in[1];
    const float* v    = (const float*)d_in[2];
    const float* e    = (const float*)d_in[3];
    const float* wq   = (const float*)d_in[4];
    const float* wk   = (const float*)d_in[5];
    const int*   esrc = (const int*)d_in[6];
    const int*   edst = (const int*)d_in[7];

    const int N = in_sizes[0] / (HEADS * CH);
    const int E = in_sizes[6];
    const int nrows = N * HEADS;

    int kn_warps  = (nrows + 7) / 8;
    int kn_blocks = (kn_warps + 7) / 8;
    kn_kernel<<<kn_blocks, 256>>>((const float4*)k, (const float4*)wk, nrows);
    rowptr_kernel<<<(N + 256) / 256, 256>>>(edst, E, N);
    attn_kernel<<<N, 256>>>((const float4*)q, (const float4*)v,
                            (const float4*)e, (const float4*)wq,
                            esrc, (float4*)d_out);
}

// round 7
// speedup vs baseline: 1.3947x; 1.3947x over previous
#include <cuda_runtime.h>

#define HEADS 8
#define CH 32
#define CH4 8              // float4 chunks per (head) row
#define NMAX 50000
#define EMAX 400000

__device__ float4 g_kn4[NMAX * HEADS * CH4];  // RMSNorm'd K, float4 layout
__device__ int    g_rowptr[NMAX + 1];

// ---------------------------------------------------------------------------
// Kernel 1: kn = RMSNorm(k)*w_k — warp handles 8 rows (2 independent chains
// per lane-group). Proven 14.8us @ ~4TB/s.
// ---------------------------------------------------------------------------
__global__ void kn_kernel(const float4* __restrict__ k4,
                          const float4* __restrict__ w4,
                          int nrows) {
    int warp = blockIdx.x * (blockDim.x >> 5) + (threadIdx.x >> 5);
    int lane = threadIdx.x & 31;
    int g = lane >> 3;
    int i = lane & 7;
    int r0 = warp * 8 + g;
    int r1 = r0 + 4;
    if (r0 >= nrows) return;
    bool has1 = r1 < nrows;

    float4 x0 = k4[r0 * CH4 + i];
    float4 x1 = has1 ? k4[r1 * CH4 + i] : make_float4(0.f, 0.f, 0.f, 0.f);

    float s0 = x0.x * x0.x + x0.y * x0.y + x0.z * x0.z + x0.w * x0.w;
    float s1 = x1.x * x1.x + x1.y * x1.y + x1.z * x1.z + x1.w * x1.w;
#pragma unroll
    for (int o = 1; o <= 4; o <<= 1) {
        s0 += __shfl_xor_sync(0xffffffffu, s0, o);
        s1 += __shfl_xor_sync(0xffffffffu, s1, o);
    }
    float r0v = rsqrtf(s0 * (1.0f / CH) + 1e-6f);
    float r1v = rsqrtf(s1 * (1.0f / CH) + 1e-6f);
    float4 w = w4[i];
    float4 y0, y1;
    y0.x = x0.x * r0v * w.x; y0.y = x0.y * r0v * w.y;
    y0.z = x0.z * r0v * w.z; y0.w = x0.w * r0v * w.w;
    g_kn4[r0 * CH4 + i] = y0;
    if (has1) {
        y1.x = x1.x * r1v * w.x; y1.y = x1.y * r1v * w.y;
        y1.z = x1.z * r1v * w.z; y1.w = x1.w * r1v * w.w;
        g_kn4[r1 * CH4 + i] = y1;
    }
}

// ---------------------------------------------------------------------------
// Kernel 2: row_ptr[d] = lower_bound(edge_dst, d)
// ---------------------------------------------------------------------------
__global__ void rowptr_kernel(const int* __restrict__ dst, int E, int N) {
    int d = blockIdx.x * blockDim.x + threadIdx.x;
    if (d > N) return;
    int lo = 0, hi = E;
    while (lo < hi) {
        int mid = (lo + hi) >> 1;
        if (dst[mid] < d) lo = mid + 1; else hi = mid;
    }
    g_rowptr[d] = lo;
}

// ---------------------------------------------------------------------------
// Kernel 3: warp = destination (ALL 8 heads). lane = h*4 + j:
//   head h (0..7), quad j (0..3); lane owns channels [j*8, j*8+8) = 2 float4s.
//   Per edge: 1 uniform src load + 6 LDG.128/lane (= full contiguous 1KB rows
//   of e, kn, v per warp), 8-FMA partial dot, 2 SHFLs (quad reduce), 1 exp.
//   No tail masking, no epilogue reduction: l replicates within each quad.
//   No running max (scores are O(8); fp32 exp cannot overflow).
// ---------------------------------------------------------------------------
__global__ void __launch_bounds__(256, 5)
attn_kernel(const float4* __restrict__ q4,
            const float4* __restrict__ v4,
            const float4* __restrict__ e4,
            const float4* __restrict__ wq4,
            const int*    __restrict__ src,
            float4* __restrict__ out4,
            int N) {
    const int d = blockIdx.x * (blockDim.x >> 5) + (threadIdx.x >> 5);
    if (d >= N) return;
    const int lane = threadIdx.x & 31;
    const int h = lane >> 2;
    const int j = lane & 3;

    const int start = g_rowptr[d];
    const int end   = g_rowptr[d + 1];

    const int bq = (d * HEADS + h) * CH4 + 2 * j;   // this lane's 2 float4s

    // RMSNorm(q) for all heads at once: quad-reduce sum of squares
    float4 qa = q4[bq], qb = q4[bq + 1];
    float ss = qa.x * qa.x + qa.y * qa.y + qa.z * qa.z + qa.w * qa.w
             + qb.x * qb.x + qb.y * qb.y + qb.z * qb.z + qb.w * qb.w;
    ss += __shfl_xor_sync(0xffffffffu, ss, 1);
    ss += __shfl_xor_sync(0xffffffffu, ss, 2);
    float rq = rsqrtf(ss * (1.0f / CH) + 1e-6f);
    float4 wa = wq4[2 * j], wb = wq4[2 * j + 1];
    qa.x *= rq * wa.x; qa.y *= rq * wa.y; qa.z *= rq * wa.z; qa.w *= rq * wa.w;
    qb.x *= rq * wb.x; qb.y *= rq * wb.y; qb.z *= rq * wb.z; qb.w *= rq * wb.w;

    const float scale = 0.1767766952966369f;  // 1/sqrt(32)
    const int loff = h * CH4 + 2 * j;         // lane offset within a 1KB row

    float  l  = 0.0f;
    float4 aa = make_float4(0.f, 0.f, 0.f, 0.f);
    float4 ab = make_float4(0.f, 0.f, 0.f, 0.f);

#pragma unroll 2
    for (int eid = start; eid < end; eid++) {
        int s = src[eid];                      // warp-uniform

        int be = eid * (HEADS * CH4) + loff;
        float4 ea = __ldcs(&e4[be]);
        float4 eb = __ldcs(&e4[be + 1]);

        int bs = s * (HEADS * CH4) + loff;
        float4 ka = g_kn4[bs], kb = g_kn4[bs + 1];
        float4 va = v4[bs],    vb = v4[bs + 1];

        // partial dot over this lane's 8 channels
        float p = qa.x * (ka.x + ea.x);
        p = fmaf(qa.y, ka.y + ea.y, p);
        p = fmaf(qa.z, ka.z + ea.z, p);
        p = fmaf(qa.w, ka.w + ea.w, p);
        p = fmaf(qb.x, kb.x + eb.x, p);
        p = fmaf(qb.y, kb.y + eb.y, p);
        p = fmaf(qb.z, kb.z + eb.z, p);
        p = fmaf(qb.w, kb.w + eb.w, p);
        p += __shfl_xor_sync(0xffffffffu, p, 1);
        p += __shfl_xor_sync(0xffffffffu, p, 2);

        float pe = __expf(p * scale);

        l += pe;
        aa.x = fmaf(pe, va.x + ea.x, aa.x);
        aa.y = fmaf(pe, va.y + ea.y, aa.y);
        aa.z = fmaf(pe, va.z + ea.z, aa.z);
        aa.w = fmaf(pe, va.w + ea.w, aa.w);
        ab.x = fmaf(pe, vb.x + eb.x, ab.x);
        ab.y = fmaf(pe, vb.y + eb.y, ab.y);
        ab.z = fmaf(pe, vb.z + eb.z, ab.z);
        ab.w = fmaf(pe, vb.w + eb.w, ab.w);
    }

    float inv = (l > 0.0f) ? 1.0f / l : 0.0f;
    float4 oa, ob;
    oa.x = aa.x * inv; oa.y = aa.y * inv; oa.z = aa.z * inv; oa.w = aa.w * inv;
    ob.x = ab.x * inv; ob.y = ab.y * inv; ob.z = ab.z * inv; ob.w = ab.w * inv;
    out4[bq]     = oa;
    out4[bq + 1] = ob;
}

// ---------------------------------------------------------------------------
extern "C" void kernel_launch(void* const* d_in, const int* in_sizes, int n_in,
                              void* d_out, int out_size) {
    const float* q    = (const float*)d_in[0];
    const float* k    = (const float*)d_in[1];
    const float* v    = (const float*)d_in[2];
    const float* e    = (const float*)d_in[3];
    const float* wq   = (const float*)d_in[4];
    const float* wk   = (const float*)d_in[5];
    const int*   esrc = (const int*)d_in[6];
    const int*   edst = (const int*)d_in[7];

    const int N = in_sizes[0] / (HEADS * CH);
    const int E = in_sizes[6];
    const int nrows = N * HEADS;

    int kn_warps  = (nrows + 7) / 8;
    int kn_blocks = (kn_warps + 7) / 8;
    kn_kernel<<<kn_blocks, 256>>>((const float4*)k, (const float4*)wk, nrows);
    rowptr_kernel<<<(N + 256) / 256, 256>>>(edst, E, N);
    attn_kernel<<<(N + 7) / 8, 256>>>((const float4*)q, (const float4*)v,
                                      (const float4*)e, (const float4*)wq,
                                      esrc, (float4*)d_out, N);
}

// round 8
// speedup vs baseline: 1.4245x; 1.0213x over previous
#include <cuda_runtime.h>
#include <cstdint>

#define HEADS 8
#define CH 32
#define CH4 8              // float4 chunks per (head) row
#define NMAX 50000
#define EMAX 400000

__device__ float4 g_kn4[NMAX * HEADS * CH4];  // RMSNorm'd K
__device__ int    g_rowptr[NMAX + 1];

// ---- 256-bit loads (sm_103a) ----------------------------------------------
__device__ __forceinline__ void ldg256(const float* p, float4& a, float4& b) {
    uint32_t u0,u1,u2,u3,u4,u5,u6,u7;
    asm volatile("ld.global.nc.v8.b32 {%0,%1,%2,%3,%4,%5,%6,%7}, [%8];"
        : "=r"(u0),"=r"(u1),"=r"(u2),"=r"(u3),
          "=r"(u4),"=r"(u5),"=r"(u6),"=r"(u7) : "l"(p));
    a.x=__uint_as_float(u0); a.y=__uint_as_float(u1);
    a.z=__uint_as_float(u2); a.w=__uint_as_float(u3);
    b.x=__uint_as_float(u4); b.y=__uint_as_float(u5);
    b.z=__uint_as_float(u6); b.w=__uint_as_float(u7);
}
__device__ __forceinline__ void ldg256_stream(const float* p, float4& a, float4& b) {
    uint32_t u0,u1,u2,u3,u4,u5,u6,u7;
    asm volatile("ld.global.nc.L2::evict_first.v8.b32 {%0,%1,%2,%3,%4,%5,%6,%7}, [%8];"
        : "=r"(u0),"=r"(u1),"=r"(u2),"=r"(u3),
          "=r"(u4),"=r"(u5),"=r"(u6),"=r"(u7) : "l"(p));
    a.x=__uint_as_float(u0); a.y=__uint_as_float(u1);
    a.z=__uint_as_float(u2); a.w=__uint_as_float(u3);
    b.x=__uint_as_float(u4); b.y=__uint_as_float(u5);
    b.z=__uint_as_float(u6); b.w=__uint_as_float(u7);
}

// ---------------------------------------------------------------------------
// Kernel 1: kn = RMSNorm(k)*w_k — 4 lanes per row (32B each), 16 rows/warp
// in 2 independent chains. 1 LDG.256 + 2 SHFL + 2 STG.128 per 8 rows.
// ---------------------------------------------------------------------------
__global__ void kn_kernel(const float* __restrict__ k,
                          const float4* __restrict__ w4,
                          int nrows) {
    int warp = blockIdx.x * (blockDim.x >> 5) + (threadIdx.x >> 5);
    int lane = threadIdx.x & 31;
    int rg = lane >> 2;          // row within group of 8
    int j  = lane & 3;           // 32B chunk within row
    int r0 = warp * 16 + rg;
    int r1 = r0 + 8;
    if (r0 >= nrows) return;
    bool has1 = r1 < nrows;

    float4 a0, b0, a1, b1;
    ldg256(k + r0 * CH + j * 8, a0, b0);
    if (has1) ldg256(k + r1 * CH + j * 8, a1, b1);
    else { a1 = make_float4(0,0,0,0); b1 = a1; }

    float s0 = a0.x*a0.x + a0.y*a0.y + a0.z*a0.z + a0.w*a0.w
             + b0.x*b0.x + b0.y*b0.y + b0.z*b0.z + b0.w*b0.w;
    float s1 = a1.x*a1.x + a1.y*a1.y + a1.z*a1.z + a1.w*a1.w
             + b1.x*b1.x + b1.y*b1.y + b1.z*b1.z + b1.w*b1.w;
    s0 += __shfl_xor_sync(0xffffffffu, s0, 1);
    s1 += __shfl_xor_sync(0xffffffffu, s1, 1);
    s0 += __shfl_xor_sync(0xffffffffu, s0, 2);
    s1 += __shfl_xor_sync(0xffffffffu, s1, 2);

    float r0v = rsqrtf(s0 * (1.0f / CH) + 1e-6f);
    float r1v = rsqrtf(s1 * (1.0f / CH) + 1e-6f);
    float4 wa = w4[2 * j], wb = w4[2 * j + 1];

    float4 y;
    y.x = a0.x*r0v*wa.x; y.y = a0.y*r0v*wa.y; y.z = a0.z*r0v*wa.z; y.w = a0.w*r0v*wa.w;
    g_kn4[r0 * CH4 + 2 * j] = y;
    y.x = b0.x*r0v*wb.x; y.y = b0.y*r0v*wb.y; y.z = b0.z*r0v*wb.z; y.w = b0.w*r0v*wb.w;
    g_kn4[r0 * CH4 + 2 * j + 1] = y;
    if (has1) {
        y.x = a1.x*r1v*wa.x; y.y = a1.y*r1v*wa.y; y.z = a1.z*r1v*wa.z; y.w = a1.w*r1v*wa.w;
        g_kn4[r1 * CH4 + 2 * j] = y;
        y.x = b1.x*r1v*wb.x; y.y = b1.y*r1v*wb.y; y.z = b1.z*r1v*wb.z; y.w = b1.w*r1v*wb.w;
        g_kn4[r1 * CH4 + 2 * j + 1] = y;
    }
}

// ---------------------------------------------------------------------------
// Kernel 2: row_ptr[d] = lower_bound(edge_dst, d)
// ---------------------------------------------------------------------------
__global__ void rowptr_kernel(const int* __restrict__ dst, int E, int N) {
    int d = blockIdx.x * blockDim.x + threadIdx.x;
    if (d > N) return;
    int lo = 0, hi = E;
    while (lo < hi) {
        int mid = (lo + hi) >> 1;
        if (dst[mid] < d) lo = mid + 1; else hi = mid;
    }
    g_rowptr[d] = lo;
}

// ---------------------------------------------------------------------------
// Kernel 3: warp = destination (all 8 heads). lane = h*4 + j; lane owns 32B.
// Per edge: 1 uniform src load + 3 LDG.256 (e streamed evict_first),
// 8-FMA partial dot, 2 SHFL quad-reduce, 1 exp, 9 FMA accumulate.
// No running max (scores O(8); fp32 exp cannot overflow).
// ---------------------------------------------------------------------------
__global__ void __launch_bounds__(256, 4)
attn_kernel(const float* __restrict__ q,
            const float* __restrict__ v,
            const float* __restrict__ e,
            const float4* __restrict__ wq4,
            const int*    __restrict__ src,
            float4* __restrict__ out4,
            int N) {
    const int d = blockIdx.x * (blockDim.x >> 5) + (threadIdx.x >> 5);
    if (d >= N) return;
    const int lane = threadIdx.x & 31;
    const int h = lane >> 2;
    const int j = lane & 3;

    const int start = g_rowptr[d];
    const int end   = g_rowptr[d + 1];

    const int loff = h * CH + j * 8;               // float offset in 1KB row
    const int bq   = d * (HEADS * CH) + loff;

    // RMSNorm(q): quad-reduced sum of squares per head
    float4 qa, qb;
    ldg256(q + bq, qa, qb);
    float ss = qa.x*qa.x + qa.y*qa.y + qa.z*qa.z + qa.w*qa.w
             + qb.x*qb.x + qb.y*qb.y + qb.z*qb.z + qb.w*qb.w;
    ss += __shfl_xor_sync(0xffffffffu, ss, 1);
    ss += __shfl_xor_sync(0xffffffffu, ss, 2);
    float rq = rsqrtf(ss * (1.0f / CH) + 1e-6f);
    float4 wa = wq4[2 * j], wb = wq4[2 * j + 1];
    qa.x *= rq * wa.x; qa.y *= rq * wa.y; qa.z *= rq * wa.z; qa.w *= rq * wa.w;
    qb.x *= rq * wb.x; qb.y *= rq * wb.y; qb.z *= rq * wb.z; qb.w *= rq * wb.w;

    const float scale = 0.1767766952966369f;  // 1/sqrt(32)

    float  l  = 0.0f;
    float4 aa = make_float4(0.f, 0.f, 0.f, 0.f);
    float4 ab = make_float4(0.f, 0.f, 0.f, 0.f);

#pragma unroll 2
    for (int eid = start; eid < end; eid++) {
        int s = src[eid];                      // warp-uniform

        float4 ea, eb, ka, kb, va, vb;
        ldg256_stream(e + (size_t)eid * (HEADS * CH) + loff, ea, eb);
        const float* kp = (const float*)g_kn4 + (size_t)s * (HEADS * CH) + loff;
        ldg256(kp, ka, kb);
        ldg256(v + (size_t)s * (HEADS * CH) + loff, va, vb);

        float p = qa.x * (ka.x + ea.x);
        p = fmaf(qa.y, ka.y + ea.y, p);
        p = fmaf(qa.z, ka.z + ea.z, p);
        p = fmaf(qa.w, ka.w + ea.w, p);
        p = fmaf(qb.x, kb.x + eb.x, p);
        p = fmaf(qb.y, kb.y + eb.y, p);
        p = fmaf(qb.z, kb.z + eb.z, p);
        p = fmaf(qb.w, kb.w + eb.w, p);
        p += __shfl_xor_sync(0xffffffffu, p, 1);
        p += __shfl_xor_sync(0xffffffffu, p, 2);

        float pe = __expf(p * scale);

        l += pe;
        aa.x = fmaf(pe, va.x + ea.x, aa.x);
        aa.y = fmaf(pe, va.y + ea.y, aa.y);
        aa.z = fmaf(pe, va.z + ea.z, aa.z);
        aa.w = fmaf(pe, va.w + ea.w, aa.w);
        ab.x = fmaf(pe, vb.x + eb.x, ab.x);
        ab.y = fmaf(pe, vb.y + eb.y, ab.y);
        ab.z = fmaf(pe, vb.z + eb.z, ab.z);
        ab.w = fmaf(pe, vb.w + eb.w, ab.w);
    }

    float inv = (l > 0.0f) ? 1.0f / l : 0.0f;
    float4 oa, ob;
    oa.x = aa.x * inv; oa.y = aa.y * inv; oa.z = aa.z * inv; oa.w = aa.w * inv;
    ob.x = ab.x * inv; ob.y = ab.y * inv; ob.z = ab.z * inv; ob.w = ab.w * inv;
    out4[bq / 4]     = oa;
    out4[bq / 4 + 1] = ob;
}

// ---------------------------------------------------------------------------
extern "C" void kernel_launch(void* const* d_in, const int* in_sizes, int n_in,
                              void* d_out, int out_size) {
    const float* q    = (const float*)d_in[0];
    const float* k    = (const float*)d_in[1];
    const float* v    = (const float*)d_in[2];
    const float* e    = (const float*)d_in[3];
    const float* wq   = (const float*)d_in[4];
    const float* wk   = (const float*)d_in[5];
    const int*   esrc = (const int*)d_in[6];
    const int*   edst = (const int*)d_in[7];

    const int N = in_sizes[0] / (HEADS * CH);
    const int E = in_sizes[6];
    const int nrows = N * HEADS;

    int kn_warps  = (nrows + 15) / 16;
    int kn_blocks = (kn_warps + 7) / 8;
    kn_kernel<<<kn_blocks, 256>>>(k, (const float4*)wk, nrows);
    rowptr_kernel<<<(N + 256) / 256, 256>>>(edst, E, N);
    attn_kernel<<<(N + 7) / 8, 256>>>(q, v, e, (const float4*)wq,
                                      esrc, (float4*)d_out, N);
}

// round 9
// speedup vs baseline: 1.4780x; 1.0375x over previous
#include <cuda_runtime.h>
#include <cuda_fp16.h>
#include <cstdint>

#define HEADS 8
#define CH 32
#define NMAX 50000
#define EMAX 400000

// Packed fp16 scratch: per (node,head) row = 128B:
//   8 chunks of [kn ch4 (8B) | v ch4 (8B)]  (chunk i covers channels i*4..i*4+3)
__device__ uint4 g_kv[NMAX * HEADS * 8];
__device__ int   g_rowptr[NMAX + 1];

__device__ __forceinline__ void ldg256f(const float* p, float4& a, float4& b) {
    uint32_t u0,u1,u2,u3,u4,u5,u6,u7;
    asm volatile("ld.global.nc.L2::evict_first.v8.b32 {%0,%1,%2,%3,%4,%5,%6,%7}, [%8];"
        : "=r"(u0),"=r"(u1),"=r"(u2),"=r"(u3),
          "=r"(u4),"=r"(u5),"=r"(u6),"=r"(u7) : "l"(p));
    a.x=__uint_as_float(u0); a.y=__uint_as_float(u1);
    a.z=__uint_as_float(u2); a.w=__uint_as_float(u3);
    b.x=__uint_as_float(u4); b.y=__uint_as_float(u5);
    b.z=__uint_as_float(u6); b.w=__uint_as_float(u7);
}
__device__ __forceinline__ void ldg256u(const void* p, uint32_t* u) {
    asm volatile("ld.global.nc.v8.b32 {%0,%1,%2,%3,%4,%5,%6,%7}, [%8];"
        : "=r"(u[0]),"=r"(u[1]),"=r"(u[2]),"=r"(u[3]),
          "=r"(u[4]),"=r"(u[5]),"=r"(u[6]),"=r"(u[7]) : "l"(p));
}
__device__ __forceinline__ uint32_t packh2(float a, float b) {
    __half2 h = __floats2half2_rn(a, b);
    return *reinterpret_cast<uint32_t*>(&h);
}
__device__ __forceinline__ float2 unpackh2(uint32_t u) {
    return __half22float2(*reinterpret_cast<const __half2*>(&u));
}

// ---------------------------------------------------------------------------
// Kernel 1: build packed kv scratch: kn = RMSNorm(k)*w_k (fp16), v (fp16),
// interleaved per 4 channels. Warp = 8 rows (R7-proven float4 style):
// g = lane>>3 selects row, i = lane&7 owns channels i*4..i*4+3.
// ---------------------------------------------------------------------------
__global__ void kv_kernel(const float4* __restrict__ k4,
                          const float4* __restrict__ v4,
                          const float4* __restrict__ w4,
                          int nrows) {
    int warp = blockIdx.x * (blockDim.x >> 5) + (threadIdx.x >> 5);
    int lane = threadIdx.x & 31;
    int g = lane >> 3;
    int i = lane & 7;
    int r0 = warp * 8 + g;
    int r1 = r0 + 4;
    if (r0 >= nrows) return;
    bool has1 = r1 < nrows;

    float4 x0 = k4[r0 * 8 + i];
    float4 u0 = v4[r0 * 8 + i];
    float4 x1 = make_float4(0,0,0,0), u1 = x1;
    if (has1) { x1 = k4[r1 * 8 + i]; u1 = v4[r1 * 8 + i]; }

    float s0 = x0.x*x0.x + x0.y*x0.y + x0.z*x0.z + x0.w*x0.w;
    float s1 = x1.x*x1.x + x1.y*x1.y + x1.z*x1.z + x1.w*x1.w;
#pragma unroll
    for (int o = 1; o <= 4; o <<= 1) {
        s0 += __shfl_xor_sync(0xffffffffu, s0, o);
        s1 += __shfl_xor_sync(0xffffffffu, s1, o);
    }
    float r0v = rsqrtf(s0 * (1.0f / CH) + 1e-6f);
    float r1v = rsqrtf(s1 * (1.0f / CH) + 1e-6f);
    float4 w = w4[i];

    uint4 st;
    st.x = packh2(x0.x * r0v * w.x, x0.y * r0v * w.y);
    st.y = packh2(x0.z * r0v * w.z, x0.w * r0v * w.w);
    st.z = packh2(u0.x, u0.y);
    st.w = packh2(u0.z, u0.w);
    g_kv[r0 * 8 + i] = st;
    if (has1) {
        st.x = packh2(x1.x * r1v * w.x, x1.y * r1v * w.y);
        st.y = packh2(x1.z * r1v * w.z, x1.w * r1v * w.w);
        st.z = packh2(u1.x, u1.y);
        st.w = packh2(u1.z, u1.w);
        g_kv[r1 * 8 + i] = st;
    }
}

// ---------------------------------------------------------------------------
// Kernel 2: row_ptr[d] = lower_bound(edge_dst, d)
// ---------------------------------------------------------------------------
__global__ void rowptr_kernel(const int* __restrict__ dst, int E, int N) {
    int d = blockIdx.x * blockDim.x + threadIdx.x;
    if (d > N) return;
    int lo = 0, hi = E;
    while (lo < hi) {
        int mid = (lo + hi) >> 1;
        if (dst[mid] < d) lo = mid + 1; else hi = mid;
    }
    g_rowptr[d] = lo;
}

// ---------------------------------------------------------------------------
// Kernel 3: warp = destination (all 8 heads). lane = h*4+j; lane owns 8 ch.
// Per edge: uniform src + 1 LDG.256 e (fp32, evict_first) + 1 LDG.256 kn+v
// (fp16 packed, 32B covers both tensors' 8 channels).
// No running max (scores O(8); fp32 exp cannot overflow).
// ---------------------------------------------------------------------------
__global__ void __launch_bounds__(256, 4)
attn_kernel(const float* __restrict__ q,
            const float* __restrict__ e,
            const float4* __restrict__ wq4,
            const int*    __restrict__ src,
            float4* __restrict__ out4,
            int N) {
    const int d = blockIdx.x * (blockDim.x >> 5) + (threadIdx.x >> 5);
    if (d >= N) return;
    const int lane = threadIdx.x & 31;
    const int h = lane >> 2;
    const int j = lane & 3;

    const int start = g_rowptr[d];
    const int end   = g_rowptr[d + 1];

    const int loff = h * CH + j * 8;               // float offset in fp32 row
    const int bq   = d * (HEADS * CH) + loff;

    // RMSNorm(q): quad-reduce sum of squares per head
    float4 qa = *(const float4*)(q + bq);
    float4 qb = *(const float4*)(q + bq + 4);
    float ss = qa.x*qa.x + qa.y*qa.y + qa.z*qa.z + qa.w*qa.w
             + qb.x*qb.x + qb.y*qb.y + qb.z*qb.z + qb.w*qb.w;
    ss += __shfl_xor_sync(0xffffffffu, ss, 1);
    ss += __shfl_xor_sync(0xffffffffu, ss, 2);
    float rq = rsqrtf(ss * (1.0f / CH) + 1e-6f);
    float4 wa = wq4[2 * j], wb = wq4[2 * j + 1];
    qa.x *= rq * wa.x; qa.y *= rq * wa.y; qa.z *= rq * wa.z; qa.w *= rq * wa.w;
    qb.x *= rq * wb.x; qb.y *= rq * wb.y; qb.z *= rq * wb.z; qb.w *= rq * wb.w;

    const float scale = 0.1767766952966369f;  // 1/sqrt(32)
    // fp16 packed row: 128B per (s,h); this lane's 32B chunk at byte j*32
    const char* kvbase = (const char*)g_kv + (size_t)h * 128 + (size_t)j * 32;

    float  l  = 0.0f;
    float4 aa = make_float4(0.f, 0.f, 0.f, 0.f);
    float4 ab = make_float4(0.f, 0.f, 0.f, 0.f);

#pragma unroll 2
    for (int eid = start; eid < end; eid++) {
        int s = src[eid];                      // warp-uniform

        float4 ea, eb;
        ldg256f(e + (size_t)eid * (HEADS * CH) + loff, ea, eb);

        uint32_t u[8];
        ldg256u(kvbase + (size_t)s * (HEADS * 128), u);
        // chunk 2j:   u0,u1 = kn ch0..3 ; u2,u3 = v ch0..3
        // chunk 2j+1: u4,u5 = kn ch4..7 ; u6,u7 = v ch4..7
        float2 k01 = unpackh2(u[0]), k23 = unpackh2(u[1]);
        float2 v01 = unpackh2(u[2]), v23 = unpackh2(u[3]);
        float2 k45 = unpackh2(u[4]), k67 = unpackh2(u[5]);
        float2 v45 = unpackh2(u[6]), v67 = unpackh2(u[7]);

        float p = qa.x * (k01.x + ea.x);
        p = fmaf(qa.y, k01.y + ea.y, p);
        p = fmaf(qa.z, k23.x + ea.z, p);
        p = fmaf(qa.w, k23.y + ea.w, p);
        p = fmaf(qb.x, k45.x + eb.x, p);
        p = fmaf(qb.y, k45.y + eb.y, p);
        p = fmaf(qb.z, k67.x + eb.z, p);
        p = fmaf(qb.w, k67.y + eb.w, p);
        p += __shfl_xor_sync(0xffffffffu, p, 1);
        p += __shfl_xor_sync(0xffffffffu, p, 2);

        float pe = __expf(p * scale);

        l += pe;
        aa.x = fmaf(pe, v01.x + ea.x, aa.x);
        aa.y = fmaf(pe, v01.y + ea.y, aa.y);
        aa.z = fmaf(pe, v23.x + ea.z, aa.z);
        aa.w = fmaf(pe, v23.y + ea.w, aa.w);
        ab.x = fmaf(pe, v45.x + eb.x, ab.x);
        ab.y = fmaf(pe, v45.y + eb.y, ab.y);
        ab.z = fmaf(pe, v67.x + eb.z, ab.z);
        ab.w = fmaf(pe, v67.y + eb.w, ab.w);
    }

    float inv = (l > 0.0f) ? 1.0f / l : 0.0f;
    float4 oa, ob;
    oa.x = aa.x * inv; oa.y = aa.y * inv; oa.z = aa.z * inv; oa.w = aa.w * inv;
    ob.x = ab.x * inv; ob.y = ab.y * inv; ob.z = ab.z * inv; ob.w = ab.w * inv;
    out4[bq / 4]     = oa;
    out4[bq / 4 + 1] = ob;
}

// ---------------------------------------------------------------------------
extern "C" void kernel_launch(void* const* d_in, const int* in_sizes, int n_in,
                              void* d_out, int out_size) {
    const float* q    = (const float*)d_in[0];
    const float* k    = (const float*)d_in[1];
    const float* v    = (const float*)d_in[2];
    const float* e    = (const float*)d_in[3];
    const float* wq   = (const float*)d_in[4];
    const float* wk   = (const float*)d_in[5];
    const int*   esrc = (const int*)d_in[6];
    const int*   edst = (const int*)d_in[7];

    const int N = in_sizes[0] / (HEADS * CH);
    const int E = in_sizes[6];
    const int nrows = N * HEADS;

    int kv_warps  = (nrows + 7) / 8;
    int kv_blocks = (kv_warps + 7) / 8;
    kv_kernel<<<kv_blocks, 256>>>((const float4*)k, (const float4*)v,
                                  (const float4*)wk, nrows);
    rowptr_kernel<<<(N + 256) / 256, 256>>>(edst, E, N);
    attn_kernel<<<(N + 7) / 8, 256>>>(q, e, (const float4*)wq,
                                      esrc, (float4*)d_out, N);
}